// round 8
// baseline (speedup 1.0000x reference)
#include <cuda_runtime.h>
#include <cuda_bf16.h>
#include <math.h>

// ---------------------------------------------------------------------------
// SMPL LBS point deformer — single fused persistent kernel.
// Inputs (metadata order):
//  0 points      (3, N)        float32
//  1 weights     (24, N)       float32
//  2 beta        (10,)         float32
//  3 theta       (24, 3)       float32
//  4 da_theta    (24, 3)       float32
//  5 shapedirs   (NV, 3, 10)   float32
//  6 v_template  (NV, 3)       float32
//  7 J_regressor (24, NV)      float32
// Output: (1, 3, N) float32
// ---------------------------------------------------------------------------

#define NJ 24
#define NV3_MAX 24576

__constant__ int c_par[NJ] = {-1,0,0,0,1,2,3,4,5,6,7,8,9,9,9,12,13,14,16,17,18,19,20,21};

__device__ float g_vshaped[NV3_MAX];
__device__ float g_J[2][NJ * 3];      // [0]=pose (shaped), [1]=da (template)
__device__ float g_A[NJ * 12];        // row-major 3x4 per joint
__device__ int   g_ctr_vs;            // v_shaped blocks done
__device__ int   g_ctr_j;             // joint blocks done
__device__ int   g_ctr_done;          // all blocks done (for reset)
__device__ volatile int g_ready;      // A matrix published

__device__ __forceinline__ unsigned long long fma2(unsigned long long a,
                                                   unsigned long long b,
                                                   unsigned long long c) {
    unsigned long long d;
    asm("fma.rn.f32x2 %0, %1, %2, %3;" : "=l"(d) : "l"(a), "l"(b), "l"(c));
    return d;
}

// ---------------------------------------------------------------------------
// The one kernel. Roles by blockIdx.x:
//   [24, 24+vb)  : compute v_shaped (distributed, coalesced)
//   [0, 24)      : wait for v_shaped, compute joint j; last one builds A
//   everyone     : wait for A, then grid-stride LBS over point groups
// ---------------------------------------------------------------------------
__global__ void __launch_bounds__(256, 4) k_fused(
    const float* __restrict__ points,
    const float* __restrict__ weights,
    const float* __restrict__ beta,
    const float* __restrict__ theta,
    const float* __restrict__ da_theta,
    const float* __restrict__ shapedirs,
    const float* __restrict__ v_template,
    const float* __restrict__ Jreg,
    float* __restrict__ out,
    int N, long long nGroups, int nv, int vb) {
    const int bid = blockIdx.x;
    const int tid = threadIdx.x;
    const int nv3 = nv * 3;
    __shared__ int s_flag;

    // ================= role: v_shaped =================
    if (bid >= NJ && bid < NJ + vb) {
        int i = (bid - NJ) * 256 + tid;
        if (i < nv3) {
            int v = i / 3, c = i - v * 3;
            const float* sd = shapedirs + (size_t)v * 30 + c * 10;
            float s = v_template[i];
#pragma unroll
            for (int k = 0; k < 10; k++) s += sd[k] * __ldg(&beta[k]);
            g_vshaped[i] = s;
        }
        __syncthreads();
        if (tid == 0) {
            __threadfence();
            atomicAdd(&g_ctr_vs, 1);
        }
    }
    // ================= role: joints + transforms =================
    else if (bid < NJ) {
        // wait for all v_shaped blocks
        if (tid == 0) {
            while (atomicAdd(&g_ctr_vs, 0) < vb) __nanosleep(64);
            s_flag = 1;
        }
        __syncthreads();
        __threadfence();

        const int j = bid;
        float p0 = 0.f, p1 = 0.f, p2 = 0.f;   // pose (shaped)
        float d0 = 0.f, d1 = 0.f, d2 = 0.f;   // da (template)
        const float* r = Jreg + (size_t)j * nv;
        for (int v = tid; v < nv; v += 256) {
            float w = r[v];
            d0 += w * v_template[v * 3 + 0];
            d1 += w * v_template[v * 3 + 1];
            d2 += w * v_template[v * 3 + 2];
            p0 += w * __ldcg(&g_vshaped[v * 3 + 0]);
            p1 += w * __ldcg(&g_vshaped[v * 3 + 1]);
            p2 += w * __ldcg(&g_vshaped[v * 3 + 2]);
        }
#pragma unroll
        for (int off = 16; off > 0; off >>= 1) {
            p0 += __shfl_down_sync(0xffffffffu, p0, off);
            p1 += __shfl_down_sync(0xffffffffu, p1, off);
            p2 += __shfl_down_sync(0xffffffffu, p2, off);
            d0 += __shfl_down_sync(0xffffffffu, d0, off);
            d1 += __shfl_down_sync(0xffffffffu, d1, off);
            d2 += __shfl_down_sync(0xffffffffu, d2, off);
        }
        __shared__ float red[8][6];
        int lane = tid & 31, warp = tid >> 5;
        if (lane == 0) {
            red[warp][0] = p0; red[warp][1] = p1; red[warp][2] = p2;
            red[warp][3] = d0; red[warp][4] = d1; red[warp][5] = d2;
        }
        __syncthreads();
        if (tid == 0) {
            float s[6] = {0, 0, 0, 0, 0, 0};
            for (int w = 0; w < 8; w++)
                for (int k = 0; k < 6; k++) s[k] += red[w][k];
            g_J[0][j * 3 + 0] = s[0]; g_J[0][j * 3 + 1] = s[1]; g_J[0][j * 3 + 2] = s[2];
            g_J[1][j * 3 + 0] = s[3]; g_J[1][j * 3 + 1] = s[4]; g_J[1][j * 3 + 2] = s[5];
            __threadfence();
            s_flag = (atomicAdd(&g_ctr_j, 1) == NJ - 1);
        }
        __syncthreads();

        if (s_flag) {
            // ---- last joint block builds the 24 A matrices ----
            __shared__ float sJ[2][NJ * 3];
            if (tid < 2 * NJ * 3) {
                int s = tid / (NJ * 3), i = tid % (NJ * 3);
                sJ[s][i] = __ldcg(&g_J[s][i]);
            }
            __syncthreads();

            __shared__ float L[2][NJ][12];
            __shared__ float G[2][NJ][12];

            if (tid < 48) {
                int s = tid / NJ;
                int jj = tid % NJ;
                const float* th = (s == 0 ? theta : da_theta) + jj * 3;
                float rx = th[0], ry = th[1], rz = th[2];
                float nrm = sqrtf(rx * rx + ry * ry + rz * rz) + 1e-8f;
                float x = rx / nrm, y = ry / nrm, z = rz / nrm;
                float c = cosf(nrm), sn = sinf(nrm), ic = 1.0f - c;
                float* Lj = L[s][jj];
                Lj[0] = c + ic * x * x;      Lj[1] = ic * x * y - sn * z;  Lj[2] = ic * x * z + sn * y;
                Lj[3] = ic * x * y + sn * z; Lj[4] = c + ic * y * y;       Lj[5] = ic * y * z - sn * x;
                Lj[6] = ic * x * z - sn * y; Lj[7] = ic * y * z + sn * x;  Lj[8] = c + ic * z * z;
                const float* J = sJ[s];
                int p = c_par[jj];
                if (p < 0) {
                    Lj[9] = J[0]; Lj[10] = J[1]; Lj[11] = J[2];
                } else {
                    Lj[9]  = J[jj * 3 + 0] - J[p * 3 + 0];
                    Lj[10] = J[jj * 3 + 1] - J[p * 3 + 1];
                    Lj[11] = J[jj * 3 + 2] - J[p * 3 + 2];
                }
            }
            __syncthreads();

            if (tid < 2) {
                int s = tid;
                for (int k = 0; k < 12; k++) G[s][0][k] = L[s][0][k];
                for (int jj = 1; jj < NJ; jj++) {
                    int p = c_par[jj];
                    const float* Gp = G[s][p];
                    const float* Lj = L[s][jj];
                    float* Gj = G[s][jj];
                    for (int rr = 0; rr < 3; rr++) {
                        for (int cc = 0; cc < 3; cc++)
                            Gj[rr * 3 + cc] = Gp[rr * 3 + 0] * Lj[0 * 3 + cc] +
                                              Gp[rr * 3 + 1] * Lj[1 * 3 + cc] +
                                              Gp[rr * 3 + 2] * Lj[2 * 3 + cc];
                        Gj[9 + rr] = Gp[rr * 3 + 0] * Lj[9] + Gp[rr * 3 + 1] * Lj[10] +
                                     Gp[rr * 3 + 2] * Lj[11] + Gp[9 + rr];
                    }
                }
                for (int jj = 0; jj < NJ; jj++) {
                    const float* J = &sJ[s][jj * 3];
                    float* Gj = G[s][jj];
                    for (int rr = 0; rr < 3; rr++)
                        Gj[9 + rr] -= Gj[rr * 3 + 0] * J[0] + Gj[rr * 3 + 1] * J[1] +
                                      Gj[rr * 3 + 2] * J[2];
                }
            }
            __syncthreads();

            if (tid < NJ) {
                int jj = tid;
                const float* P = G[0][jj];   // pose
                const float* D = G[1][jj];   // da (rigid)
                float AR[9];
                for (int rr = 0; rr < 3; rr++)
                    for (int cc = 0; cc < 3; cc++)
                        AR[rr * 3 + cc] = P[rr * 3 + 0] * D[cc * 3 + 0] +
                                          P[rr * 3 + 1] * D[cc * 3 + 1] +
                                          P[rr * 3 + 2] * D[cc * 3 + 2];
                float ti[3];
                for (int rr = 0; rr < 3; rr++)
                    ti[rr] = -(D[0 * 3 + rr] * D[9] + D[1 * 3 + rr] * D[10] +
                               D[2 * 3 + rr] * D[11]);
                for (int rr = 0; rr < 3; rr++) {
                    float at = P[rr * 3 + 0] * ti[0] + P[rr * 3 + 1] * ti[1] +
                               P[rr * 3 + 2] * ti[2] + P[9 + rr];
                    g_A[jj * 12 + rr * 4 + 0] = AR[rr * 3 + 0];
                    g_A[jj * 12 + rr * 4 + 1] = AR[rr * 3 + 1];
                    g_A[jj * 12 + rr * 4 + 2] = AR[rr * 3 + 2];
                    g_A[jj * 12 + rr * 4 + 3] = at;
                }
            }
            __syncthreads();
            if (tid == 0) {
                __threadfence();
                g_ready = 1;       // publish A
            }
        }
    }

    // ================= everyone: wait for A, then LBS =================
    if (tid == 0) {
        while (g_ready == 0) __nanosleep(64);
        s_flag = 1;
    }
    __syncthreads();
    __threadfence();

    __shared__ __align__(16) unsigned long long sA[NJ * 12];  // {a,a} packed
    for (int i = tid; i < NJ * 12; i += 256) {
        unsigned long long u = (unsigned long long)__float_as_uint(__ldcg(&g_A[i]));
        sA[i] = u | (u << 32);
    }
    __syncthreads();

    const long long stride = (long long)gridDim.x * 256;
    for (long long g = (long long)bid * 256 + tid; g < nGroups; g += stride) {
        const ulonglong2 X = reinterpret_cast<const ulonglong2*>(points)[g];
        const ulonglong2 Y = reinterpret_cast<const ulonglong2*>(points + (size_t)N)[g];
        const ulonglong2 Z = reinterpret_cast<const ulonglong2*>(points + 2 * (size_t)N)[g];

        unsigned long long vxa = 0ull, vya = 0ull, vza = 0ull;
        unsigned long long vxb = 0ull, vyb = 0ull, vzb = 0ull;

#pragma unroll
        for (int j = 0; j < NJ; j++) {
            const ulonglong2 W =
                reinterpret_cast<const ulonglong2*>(weights + (size_t)j * N)[g];
            const ulonglong2* ap = reinterpret_cast<const ulonglong2*>(&sA[j * 12]);
            const ulonglong2 a01 = ap[0], a23 = ap[1], a45 = ap[2];
            const ulonglong2 a67 = ap[3], a89 = ap[4], aAB = ap[5];
            unsigned long long s;
            s = fma2(a01.x, X.x, a23.y); s = fma2(a01.y, Y.x, s); s = fma2(a23.x, Z.x, s); vxa = fma2(W.x, s, vxa);
            s = fma2(a45.x, X.x, a67.y); s = fma2(a45.y, Y.x, s); s = fma2(a67.x, Z.x, s); vya = fma2(W.x, s, vya);
            s = fma2(a89.x, X.x, aAB.y); s = fma2(a89.y, Y.x, s); s = fma2(aAB.x, Z.x, s); vza = fma2(W.x, s, vza);
            s = fma2(a01.x, X.y, a23.y); s = fma2(a01.y, Y.y, s); s = fma2(a23.x, Z.y, s); vxb = fma2(W.y, s, vxb);
            s = fma2(a45.x, X.y, a67.y); s = fma2(a45.y, Y.y, s); s = fma2(a67.x, Z.y, s); vyb = fma2(W.y, s, vyb);
            s = fma2(a89.x, X.y, aAB.y); s = fma2(a89.y, Y.y, s); s = fma2(aAB.x, Z.y, s); vzb = fma2(W.y, s, vzb);
        }

        ulonglong2 o;
        o.x = vxa; o.y = vxb; reinterpret_cast<ulonglong2*>(out)[g] = o;
        o.x = vya; o.y = vyb; reinterpret_cast<ulonglong2*>(out + (size_t)N)[g] = o;
        o.x = vza; o.y = vzb; reinterpret_cast<ulonglong2*>(out + 2 * (size_t)N)[g] = o;
    }

    // ================= reset state for next graph replay =================
    __syncthreads();
    if (tid == 0) {
        __threadfence();
        if (atomicAdd(&g_ctr_done, 1) == (int)gridDim.x - 1) {
            g_ctr_vs = 0;
            g_ctr_j = 0;
            g_ctr_done = 0;
            g_ready = 0;
            __threadfence();
        }
    }
}

// Scalar fallback main pass (N % 4 != 0 — not hit for this problem).
__global__ void k_lbs_scalar(const float* __restrict__ points,
                             const float* __restrict__ weights,
                             float* __restrict__ out, int N) {
    __shared__ float sA[NJ * 12];
    for (int i = threadIdx.x; i < NJ * 12; i += blockDim.x) sA[i] = __ldcg(&g_A[i]);
    __syncthreads();
    long long n = (long long)blockIdx.x * blockDim.x + threadIdx.x;
    if (n >= N) return;
    float px = points[n], py = points[(size_t)N + n], pz = points[2 * (size_t)N + n];
    float vx = 0.f, vy = 0.f, vz = 0.f;
#pragma unroll
    for (int j = 0; j < NJ; j++) {
        float w = weights[(size_t)j * N + n];
        const float* a = &sA[j * 12];
        vx += w * (a[0] * px + a[1] * py + a[2]  * pz + a[3]);
        vy += w * (a[4] * px + a[5] * py + a[6]  * pz + a[7]);
        vz += w * (a[8] * px + a[9] * py + a[10] * pz + a[11]);
    }
    out[n] = vx; out[(size_t)N + n] = vy; out[2 * (size_t)N + n] = vz;
}

// ---------------------------------------------------------------------------
extern "C" void kernel_launch(void* const* d_in, const int* in_sizes, int n_in,
                              void* d_out, int out_size) {
    const float* points      = (const float*)d_in[0];
    const float* weights     = (const float*)d_in[1];
    const float* beta        = (const float*)d_in[2];
    const float* theta       = (const float*)d_in[3];
    const float* da_theta    = (const float*)d_in[4];
    const float* shapedirs   = (const float*)d_in[5];
    const float* v_template  = (const float*)d_in[6];
    const float* J_regressor = (const float*)d_in[7];

    int N  = in_sizes[0] / 3;          // number of points
    int NV = in_sizes[5] / 30;         // template vertex count
    int vb = (NV * 3 + 255) / 256;     // v_shaped blocks

    if ((N & 3) == 0) {
        long long nGroups = (long long)N / 4;
        int persist = 148 * 4;                       // one full wave at occ 4
        long long needed = (nGroups + 255) / 256;
        int grid = (int)(needed < persist ? needed : persist);
        if (grid < NJ + vb) grid = NJ + vb;          // prep roles must exist
        k_fused<<<grid, 256>>>(points, weights, beta, theta, da_theta,
                               shapedirs, v_template, J_regressor,
                               (float*)d_out, N, nGroups, NV, vb);
    } else {
        // prep-only fused launch (grid sized for prep roles), then scalar pass
        k_fused<<<NJ + vb, 256>>>(points, weights, beta, theta, da_theta,
                                  shapedirs, v_template, J_regressor,
                                  (float*)d_out, N, 0, NV, vb);
        int blocks = (N + 255) / 256;
        k_lbs_scalar<<<blocks, 256>>>(points, weights, (float*)d_out, N);
    }
}

// round 9
// speedup vs baseline: 5.1417x; 5.1417x over previous
#include <cuda_runtime.h>
#include <cuda_bf16.h>
#include <math.h>

// ---------------------------------------------------------------------------
// SMPL LBS point deformer — 2-kernel version (wide prep + heavy pass).
// Inputs (metadata order):
//  0 points      (3, N)        float32
//  1 weights     (24, N)       float32
//  2 beta        (10,)         float32
//  3 theta       (24, 3)       float32
//  4 da_theta    (24, 3)       float32
//  5 shapedirs   (NV, 3, 10)   float32
//  6 v_template  (NV, 3)       float32
//  7 J_regressor (24, NV)      float32
// Output: (1, 3, N) float32
//
// Key identity: J_pose = Jreg@v_template + (Jreg@shapedirs)@beta
//               J_da   = Jreg@v_template
// so no v_shaped intermediate is needed at all.
// ---------------------------------------------------------------------------

#define NJ 24
#define NSPLIT 8          // v-dimension splits per joint -> grid = 24*8 = 192
#define NACC 33           // 3 template dots + 30 shapedir dots

__constant__ int c_par[NJ] = {-1,0,0,0,1,2,3,4,5,6,7,8,9,9,9,12,13,14,16,17,18,19,20,21};

__device__ float g_partial[NJ * NSPLIT * NACC];
__device__ float g_A[NJ * 12];     // row-major 3x4 per joint
__device__ int   g_ctr;            // zero-init; finisher resets each run

// ---------------------------------------------------------------------------
// Kernel 1: grid (NJ*NSPLIT) blocks, 256 threads.
// Block (j,s) computes partial sums over its v-range:
//   acc[0..2]  = sum_v w[j][v] * v_template[v][c]
//   acc[3+m]   = sum_v w[j][v] * shapedirs[v][m]   (m = c*10+k)
// Last block to finish reduces all partials and builds the 24 A matrices.
// ---------------------------------------------------------------------------
__global__ void __launch_bounds__(256) k_prep(
    const float* __restrict__ Jreg,
    const float* __restrict__ v_template,
    const float* __restrict__ shapedirs,
    const float* __restrict__ beta,
    const float* __restrict__ theta,
    const float* __restrict__ da_theta,
    int nv) {
    const int bx  = blockIdx.x;
    const int j   = bx / NSPLIT;
    const int sp  = bx % NSPLIT;
    const int tid = threadIdx.x;
    const int chunk = (nv + NSPLIT - 1) / NSPLIT;
    const int v0 = sp * chunk;
    const int v1 = min(nv, v0 + chunk);

    float acc[NACC];
#pragma unroll
    for (int k = 0; k < NACC; k++) acc[k] = 0.f;

    const float* r = Jreg + (size_t)j * nv;
    for (int v = v0 + tid; v < v1; v += 256) {
        float w = r[v];
        acc[0] += w * v_template[v * 3 + 0];
        acc[1] += w * v_template[v * 3 + 1];
        acc[2] += w * v_template[v * 3 + 2];
        const float* sd = shapedirs + (size_t)v * 30;
#pragma unroll
        for (int m = 0; m < 30; m++) acc[3 + m] += w * sd[m];
    }

    // block reduction: warp shuffles -> shared -> threads 0..32 finalize
    __shared__ float red[8][NACC];
    int lane = tid & 31, warp = tid >> 5;
#pragma unroll
    for (int k = 0; k < NACC; k++) {
        float v = acc[k];
#pragma unroll
        for (int off = 16; off > 0; off >>= 1)
            v += __shfl_down_sync(0xffffffffu, v, off);
        if (lane == 0) red[warp][k] = v;
    }
    __syncthreads();
    if (tid < NACC) {
        float s = 0.f;
#pragma unroll
        for (int w = 0; w < 8; w++) s += red[w][tid];
        g_partial[bx * NACC + tid] = s;
    }
    __syncthreads();

    __shared__ int s_last;
    if (tid == 0) {
        __threadfence();
        s_last = (atomicAdd(&g_ctr, 1) == NJ * NSPLIT - 1);
    }
    __syncthreads();
    if (!s_last) return;
    __threadfence();

    // ---------------- finisher: reduce partials, build A ----------------
    __shared__ float sP[NJ][NACC];
    for (int i = tid; i < NJ * NACC; i += 256) {
        int jj = i / NACC, c = i % NACC;
        float s = 0.f;
#pragma unroll
        for (int sp2 = 0; sp2 < NSPLIT; sp2++)
            s += __ldcg(&g_partial[(jj * NSPLIT + sp2) * NACC + c]);
        sP[jj][c] = s;
    }
    __syncthreads();

    __shared__ float sJ[2][NJ * 3];    // [0]=pose, [1]=da
    if (tid < NJ) {
        int jj = tid;
        float b[10];
#pragma unroll
        for (int k = 0; k < 10; k++) b[k] = __ldg(&beta[k]);
#pragma unroll
        for (int c = 0; c < 3; c++) {
            float jd = sP[jj][c];
            float jp = jd;
#pragma unroll
            for (int k = 0; k < 10; k++) jp += sP[jj][3 + c * 10 + k] * b[k];
            sJ[0][jj * 3 + c] = jp;
            sJ[1][jj * 3 + c] = jd;
        }
    }
    __syncthreads();

    __shared__ float L[2][NJ][12];
    __shared__ float G[2][NJ][12];

    if (tid < 48) {
        int s = tid / NJ;          // 0 = pose, 1 = da
        int jj = tid % NJ;
        const float* th = (s == 0 ? theta : da_theta) + jj * 3;
        float rx = th[0], ry = th[1], rz = th[2];
        float nrm = sqrtf(rx * rx + ry * ry + rz * rz) + 1e-8f;
        float x = rx / nrm, y = ry / nrm, z = rz / nrm;
        float c = cosf(nrm), sn = sinf(nrm), ic = 1.0f - c;
        float* Lj = L[s][jj];
        Lj[0] = c + ic * x * x;      Lj[1] = ic * x * y - sn * z;  Lj[2] = ic * x * z + sn * y;
        Lj[3] = ic * x * y + sn * z; Lj[4] = c + ic * y * y;       Lj[5] = ic * y * z - sn * x;
        Lj[6] = ic * x * z - sn * y; Lj[7] = ic * y * z + sn * x;  Lj[8] = c + ic * z * z;
        const float* J = sJ[s];
        int p = c_par[jj];
        if (p < 0) {
            Lj[9] = J[0]; Lj[10] = J[1]; Lj[11] = J[2];
        } else {
            Lj[9]  = J[jj * 3 + 0] - J[p * 3 + 0];
            Lj[10] = J[jj * 3 + 1] - J[p * 3 + 1];
            Lj[11] = J[jj * 3 + 2] - J[p * 3 + 2];
        }
    }
    __syncthreads();

    if (tid < 2) {
        int s = tid;
        for (int k = 0; k < 12; k++) G[s][0][k] = L[s][0][k];
        for (int jj = 1; jj < NJ; jj++) {
            int p = c_par[jj];
            const float* Gp = G[s][p];
            const float* Lj = L[s][jj];
            float* Gj = G[s][jj];
            for (int rr = 0; rr < 3; rr++) {
                for (int cc = 0; cc < 3; cc++)
                    Gj[rr * 3 + cc] = Gp[rr * 3 + 0] * Lj[0 * 3 + cc] +
                                      Gp[rr * 3 + 1] * Lj[1 * 3 + cc] +
                                      Gp[rr * 3 + 2] * Lj[2 * 3 + cc];
                Gj[9 + rr] = Gp[rr * 3 + 0] * Lj[9] + Gp[rr * 3 + 1] * Lj[10] +
                             Gp[rr * 3 + 2] * Lj[11] + Gp[9 + rr];
            }
        }
        // pack: t -= R @ J_rest
        for (int jj = 0; jj < NJ; jj++) {
            const float* J = &sJ[s][jj * 3];
            float* Gj = G[s][jj];
            for (int rr = 0; rr < 3; rr++)
                Gj[9 + rr] -= Gj[rr * 3 + 0] * J[0] + Gj[rr * 3 + 1] * J[1] +
                              Gj[rr * 3 + 2] * J[2];
        }
    }
    __syncthreads();

    if (tid < NJ) {
        int jj = tid;
        const float* P = G[0][jj];   // pose
        const float* D = G[1][jj];   // da (rigid: R orthogonal)
        float AR[9];
        for (int rr = 0; rr < 3; rr++)
            for (int cc = 0; cc < 3; cc++)
                AR[rr * 3 + cc] = P[rr * 3 + 0] * D[cc * 3 + 0] +
                                  P[rr * 3 + 1] * D[cc * 3 + 1] +
                                  P[rr * 3 + 2] * D[cc * 3 + 2];
        float ti[3];
        for (int rr = 0; rr < 3; rr++)
            ti[rr] = -(D[0 * 3 + rr] * D[9] + D[1 * 3 + rr] * D[10] +
                       D[2 * 3 + rr] * D[11]);
        for (int rr = 0; rr < 3; rr++) {
            float at = P[rr * 3 + 0] * ti[0] + P[rr * 3 + 1] * ti[1] +
                       P[rr * 3 + 2] * ti[2] + P[9 + rr];
            g_A[jj * 12 + rr * 4 + 0] = AR[rr * 3 + 0];
            g_A[jj * 12 + rr * 4 + 1] = AR[rr * 3 + 1];
            g_A[jj * 12 + rr * 4 + 2] = AR[rr * 3 + 2];
            g_A[jj * 12 + rr * 4 + 3] = at;
        }
    }
    if (tid == 0) g_ctr = 0;   // reset for next replay (deterministic)
}

// ---------------------------------------------------------------------------
// Kernel 2: heavy per-point pass — identical to the measured 41.6us version,
// plus streaming load/store hints (.cs) for the single-use bulk data.
// ---------------------------------------------------------------------------
__device__ __forceinline__ unsigned long long fma2(unsigned long long a,
                                                   unsigned long long b,
                                                   unsigned long long c) {
    unsigned long long d;
    asm("fma.rn.f32x2 %0, %1, %2, %3;" : "=l"(d) : "l"(a), "l"(b), "l"(c));
    return d;
}

__device__ __forceinline__ ulonglong2 ldcs2(const ulonglong2* p) {
    ulonglong2 v;
    asm("ld.global.cs.v2.u64 {%0, %1}, [%2];"
        : "=l"(v.x), "=l"(v.y) : "l"(p));
    return v;
}

__device__ __forceinline__ void stcs2(ulonglong2* p, ulonglong2 v) {
    asm("st.global.cs.v2.u64 [%0], {%1, %2};" :: "l"(p), "l"(v.x), "l"(v.y)
        : "memory");
}

__global__ void __launch_bounds__(256, 4) k_lbs_vec(
    const float* __restrict__ points, const float* __restrict__ weights,
    float* __restrict__ out, int N, long long nGroups) {
    __shared__ __align__(16) unsigned long long sA[NJ * 12];  // {a,a} packed
    for (int i = threadIdx.x; i < NJ * 12; i += blockDim.x) {
        unsigned long long u = (unsigned long long)__float_as_uint(g_A[i]);
        sA[i] = u | (u << 32);
    }
    __syncthreads();

    long long g = (long long)blockIdx.x * blockDim.x + threadIdx.x;
    if (g >= nGroups) return;

    const ulonglong2 X = ldcs2(reinterpret_cast<const ulonglong2*>(points) + g);
    const ulonglong2 Y = ldcs2(reinterpret_cast<const ulonglong2*>(points + (size_t)N) + g);
    const ulonglong2 Z = ldcs2(reinterpret_cast<const ulonglong2*>(points + 2 * (size_t)N) + g);

    unsigned long long vxa = 0ull, vya = 0ull, vza = 0ull;
    unsigned long long vxb = 0ull, vyb = 0ull, vzb = 0ull;

#pragma unroll
    for (int j = 0; j < NJ; j++) {
        const ulonglong2 W =
            ldcs2(reinterpret_cast<const ulonglong2*>(weights + (size_t)j * N) + g);
        const ulonglong2* ap = reinterpret_cast<const ulonglong2*>(&sA[j * 12]);
        const ulonglong2 a01 = ap[0], a23 = ap[1], a45 = ap[2];
        const ulonglong2 a67 = ap[3], a89 = ap[4], aAB = ap[5];
        unsigned long long s;
        // pair a (points 4g, 4g+1)
        s = fma2(a01.x, X.x, a23.y); s = fma2(a01.y, Y.x, s); s = fma2(a23.x, Z.x, s); vxa = fma2(W.x, s, vxa);
        s = fma2(a45.x, X.x, a67.y); s = fma2(a45.y, Y.x, s); s = fma2(a67.x, Z.x, s); vya = fma2(W.x, s, vya);
        s = fma2(a89.x, X.x, aAB.y); s = fma2(a89.y, Y.x, s); s = fma2(aAB.x, Z.x, s); vza = fma2(W.x, s, vza);
        // pair b (points 4g+2, 4g+3)
        s = fma2(a01.x, X.y, a23.y); s = fma2(a01.y, Y.y, s); s = fma2(a23.x, Z.y, s); vxb = fma2(W.y, s, vxb);
        s = fma2(a45.x, X.y, a67.y); s = fma2(a45.y, Y.y, s); s = fma2(a67.x, Z.y, s); vyb = fma2(W.y, s, vyb);
        s = fma2(a89.x, X.y, aAB.y); s = fma2(a89.y, Y.y, s); s = fma2(aAB.x, Z.y, s); vzb = fma2(W.y, s, vzb);
    }

    ulonglong2 o;
    o.x = vxa; o.y = vxb; stcs2(reinterpret_cast<ulonglong2*>(out) + g, o);
    o.x = vya; o.y = vyb; stcs2(reinterpret_cast<ulonglong2*>(out + (size_t)N) + g, o);
    o.x = vza; o.y = vzb; stcs2(reinterpret_cast<ulonglong2*>(out + 2 * (size_t)N) + g, o);
}

// Scalar fallback (only used if N % 4 != 0 — not the case for this problem).
__global__ void k_lbs_scalar(const float* __restrict__ points,
                             const float* __restrict__ weights,
                             float* __restrict__ out, int N) {
    __shared__ float sA[NJ * 12];
    for (int i = threadIdx.x; i < NJ * 12; i += blockDim.x) sA[i] = g_A[i];
    __syncthreads();
    long long n = (long long)blockIdx.x * blockDim.x + threadIdx.x;
    if (n >= N) return;
    float px = points[n], py = points[(size_t)N + n], pz = points[2 * (size_t)N + n];
    float vx = 0.f, vy = 0.f, vz = 0.f;
#pragma unroll
    for (int j = 0; j < NJ; j++) {
        float w = weights[(size_t)j * N + n];
        const float* a = &sA[j * 12];
        vx += w * (a[0] * px + a[1] * py + a[2]  * pz + a[3]);
        vy += w * (a[4] * px + a[5] * py + a[6]  * pz + a[7]);
        vz += w * (a[8] * px + a[9] * py + a[10] * pz + a[11]);
    }
    out[n] = vx; out[(size_t)N + n] = vy; out[2 * (size_t)N + n] = vz;
}

// ---------------------------------------------------------------------------
extern "C" void kernel_launch(void* const* d_in, const int* in_sizes, int n_in,
                              void* d_out, int out_size) {
    const float* points      = (const float*)d_in[0];
    const float* weights     = (const float*)d_in[1];
    const float* beta        = (const float*)d_in[2];
    const float* theta       = (const float*)d_in[3];
    const float* da_theta    = (const float*)d_in[4];
    const float* shapedirs   = (const float*)d_in[5];
    const float* v_template  = (const float*)d_in[6];
    const float* J_regressor = (const float*)d_in[7];

    int N  = in_sizes[0] / 3;          // number of points
    int NV = in_sizes[5] / 30;         // template vertex count

    // wide prep: partial joint sums + (last block) transforms. grid=192>=148.
    k_prep<<<NJ * NSPLIT, 256>>>(J_regressor, v_template, shapedirs, beta,
                                 theta, da_theta, NV);

    // main pass
    if ((N & 3) == 0) {
        long long nGroups = (long long)N / 4;
        int blocks = (int)((nGroups + 255) / 256);
        k_lbs_vec<<<blocks, 256>>>(points, weights, (float*)d_out, N, nGroups);
    } else {
        int blocks = (N + 255) / 256;
        k_lbs_scalar<<<blocks, 256>>>(points, weights, (float*)d_out, N);
    }
}